// round 2
// baseline (speedup 1.0000x reference)
#include <cuda_runtime.h>
#include <math.h>

#define B 32
#define T 128
#define BT 4096
#define E 1024
#define H 1024
#define G 4096
#define V 32000
#define HP 1028   // padded h row length in smem (float4-aligned, low-conflict)

// ---------------- device scratch (no allocations allowed) ----------------
__device__ __align__(16) float g_xemb[BT * E];     // 16 MB embedded inputs
__device__ __align__(16) float g_gx[BT * G];       // 64 MB input-path gates (reused per layer)
__device__ __align__(16) float g_hseq0[BT * H];    // 16 MB layer-0 outputs
__device__ __align__(16) float g_hseq1[BT * H];    // 16 MB layer-1 outputs
__device__ __align__(16) float g_h0[B * H];
__device__ __align__(16) float g_h1[B * H];
__device__ __align__(16) float g_c[B * H];

// ---------------- embedding gather ----------------
__global__ void embed_kernel(const int* __restrict__ idx, const float* __restrict__ emb) {
    int row = blockIdx.x;                       // row = b*T + t
    int tok = idx[row];
    const float4* src = (const float4*)(emb + (size_t)tok * E);
    float4* dst = (float4*)(g_xemb + (size_t)row * E);
    dst[threadIdx.x] = src[threadIdx.x];        // 256 threads * 4 = 1024 floats
}

__global__ void zero_state_kernel() {
    int i = blockIdx.x * blockDim.x + threadIdx.x;
    if (i < B * H) { g_h0[i] = 0.f; g_c[i] = 0.f; }
}

// ---------------- classic 128x128x8 register-tiled SGEMM + bias ----------------
// C[M,N] = A[M,K] @ Bm[K,N] + bias[N];  M,N multiples of 128, K multiple of 8.
__global__ __launch_bounds__(256) void sgemm_bias(
    const float* __restrict__ A, const float* __restrict__ Bm,
    const float* __restrict__ bias, float* __restrict__ C,
    int M, int N, int K)
{
    __shared__ float As[8][128];
    __shared__ float Bs[8][128];
    int tid = threadIdx.x;
    int bx = blockIdx.x, by = blockIdx.y;
    int tx = tid & 15, ty = tid >> 4;

    const float* Ab = A + (size_t)by * 128 * K;
    const float* Bb = Bm + (size_t)bx * 128;

    int arow = tid >> 1, acol = (tid & 1) * 4;
    int brow = tid >> 5, bcol = (tid & 31) * 4;

    float acc[8][8];
#pragma unroll
    for (int i = 0; i < 8; i++)
#pragma unroll
        for (int j = 0; j < 8; j++) acc[i][j] = 0.f;

    for (int kt = 0; kt < K; kt += 8) {
        float4 av = *(const float4*)(Ab + (size_t)arow * K + kt + acol);
        float4 bv = *(const float4*)(Bb + (size_t)(kt + brow) * N + bcol);
        __syncthreads();
        As[acol + 0][arow] = av.x;
        As[acol + 1][arow] = av.y;
        As[acol + 2][arow] = av.z;
        As[acol + 3][arow] = av.w;
        *(float4*)&Bs[brow][bcol] = bv;
        __syncthreads();
#pragma unroll
        for (int k = 0; k < 8; k++) {
            float ar[8], br[8];
            *(float4*)&ar[0] = *(const float4*)&As[k][ty * 8];
            *(float4*)&ar[4] = *(const float4*)&As[k][ty * 8 + 4];
            *(float4*)&br[0] = *(const float4*)&Bs[k][tx * 8];
            *(float4*)&br[4] = *(const float4*)&Bs[k][tx * 8 + 4];
#pragma unroll
            for (int i = 0; i < 8; i++)
#pragma unroll
                for (int j = 0; j < 8; j++)
                    acc[i][j] = fmaf(ar[i], br[j], acc[i][j]);
        }
    }

#pragma unroll
    for (int i = 0; i < 8; i++) {
        int row = by * 128 + ty * 8 + i;
        int col = bx * 128 + tx * 8;
        float* Cp = C + (size_t)row * N + col;
        const float* bp = bias + col;
        float4 o0, o1;
        o0.x = acc[i][0] + bp[0]; o0.y = acc[i][1] + bp[1];
        o0.z = acc[i][2] + bp[2]; o0.w = acc[i][3] + bp[3];
        o1.x = acc[i][4] + bp[4]; o1.y = acc[i][5] + bp[5];
        o1.z = acc[i][6] + bp[6]; o1.w = acc[i][7] + bp[7];
        *(float4*)Cp = o0;
        *(float4*)(Cp + 4) = o1;
    }
}

// ---------------- fused LSTM timestep ----------------
// Block = 8 hidden units (j0..j0+7) x 4 gates x 32 batches, split-K=4 in-block.
// gates(b,col) = gx[(b*T+t), col] + sum_k h_in[b,k] * Wh[k, col], then cell update.
#define FMA4(ai, hv, wv)                                   \
    acc[ai][0] = fmaf(hv, wv.x, acc[ai][0]);               \
    acc[ai][1] = fmaf(hv, wv.y, acc[ai][1]);               \
    acc[ai][2] = fmaf(hv, wv.z, acc[ai][2]);               \
    acc[ai][3] = fmaf(hv, wv.w, acc[ai][3]);

__global__ __launch_bounds__(256) void lstm_step(
    const float* __restrict__ gx,     // [BT][G] input-path gates (+bias)
    const float* __restrict__ Wh,     // [H][G] recurrent weight slice
    const float* __restrict__ h_in,   // [B][H]
    float* __restrict__ h_out,        // [B][H]
    float* __restrict__ c_st,         // [B][H]
    float* __restrict__ hseq,         // [BT][H]
    int t)
{
    extern __shared__ float sm[];
    float* h_sm  = sm;                    // 32 * HP
    float* red   = sm + 32 * HP;          // 3 * 1024 split-K partials
    float* gates = red + 3 * 1024;        // 32 * 33

    int tid = threadIdx.x;

    // stage h into smem (coalesced float4 copy)
    const float4* h4 = (const float4*)h_in;
#pragma unroll
    for (int it = 0; it < 32; it++) {
        int q = tid + it * 256;           // 0..8191
        int b = q >> 8, k4 = q & 255;
        float4 v = h4[q];
        *(float4*)&h_sm[b * HP + k4 * 4] = v;
    }
    __syncthreads();

    int ks = tid >> 6;                    // k-slice 0..3
    int r  = tid & 63;
    int bg = r >> 3;                      // batch group 0..7 (4 batches each)
    int cq = r & 7;                       // column quad 0..7
    int g  = cq >> 1;                     // gate 0..3 (i,j,f,o)
    int jo4 = (cq & 1) * 4;               // j offset within the 8-unit tile
    int j0 = blockIdx.x * 8;

    const float4* W4 = (const float4*)Wh + ((g * H + j0 + jo4) >> 2);
    const float* hb0p = &h_sm[(bg * 4 + 0) * HP];
    const float* hb1p = &h_sm[(bg * 4 + 1) * HP];
    const float* hb2p = &h_sm[(bg * 4 + 2) * HP];
    const float* hb3p = &h_sm[(bg * 4 + 3) * HP];

    float acc[4][4];
#pragma unroll
    for (int i = 0; i < 4; i++)
#pragma unroll
        for (int j = 0; j < 4; j++) acc[i][j] = 0.f;

    int k0 = ks * 256;
#pragma unroll 2
    for (int k = k0; k < k0 + 256; k += 4) {
        float4 w0 = W4[(size_t)(k + 0) * (G / 4)];
        float4 w1 = W4[(size_t)(k + 1) * (G / 4)];
        float4 w2 = W4[(size_t)(k + 2) * (G / 4)];
        float4 w3 = W4[(size_t)(k + 3) * (G / 4)];
        float4 ha = *(const float4*)&hb0p[k];
        float4 hb = *(const float4*)&hb1p[k];
        float4 hc = *(const float4*)&hb2p[k];
        float4 hd = *(const float4*)&hb3p[k];
        FMA4(0, ha.x, w0) FMA4(1, hb.x, w0) FMA4(2, hc.x, w0) FMA4(3, hd.x, w0)
        FMA4(0, ha.y, w1) FMA4(1, hb.y, w1) FMA4(2, hc.y, w1) FMA4(3, hd.y, w1)
        FMA4(0, ha.z, w2) FMA4(1, hb.z, w2) FMA4(2, hc.z, w2) FMA4(3, hd.z, w2)
        FMA4(0, ha.w, w3) FMA4(1, hb.w, w3) FMA4(2, hc.w, w3) FMA4(3, hd.w, w3)
    }

    // split-K reduction
    if (ks > 0) {
#pragma unroll
        for (int i = 0; i < 4; i++)
#pragma unroll
            for (int j = 0; j < 4; j++)
                red[(ks - 1) * 1024 + r * 16 + i * 4 + j] = acc[i][j];
    }
    __syncthreads();
    if (ks == 0) {
#pragma unroll
        for (int i = 0; i < 4; i++)
#pragma unroll
            for (int j = 0; j < 4; j++) {
                int cell = r * 16 + i * 4 + j;
                float v = acc[i][j] + red[cell] + red[1024 + cell] + red[2048 + cell];
                int b = bg * 4 + i;
                gates[b * 33 + g * 8 + jo4 + j] = v;
            }
    }
    __syncthreads();

    // fused cell update: thread -> (b, j)
    {
        int b = tid >> 3;
        int j = tid & 7;
        int jg = j0 + j;
        const float* gxr = gx + (size_t)(b * T + t) * G;
        float vi = gates[b * 33 +  0 + j] + gxr[0 * H + jg];
        float vj = gates[b * 33 +  8 + j] + gxr[1 * H + jg];
        float vf = gates[b * 33 + 16 + j] + gxr[2 * H + jg];
        float vo = gates[b * 33 + 24 + j] + gxr[3 * H + jg];
        float cold = c_st[b * H + jg];
        float si = 1.f / (1.f + expf(-vi));
        float sf = 1.f / (1.f + expf(-(vf + 1.f)));
        float so = 1.f / (1.f + expf(-vo));
        float cnew = sf * cold + si * tanhf(vj);
        float hnew = so * tanhf(cnew);
        c_st[b * H + jg] = cnew;
        h_out[b * H + jg] = hnew;
        hseq[(size_t)(b * T + t) * H + jg] = hnew;
    }
}

// ---------------- launcher ----------------
extern "C" void kernel_launch(void* const* d_in, const int* in_sizes, int n_in,
                              void* d_out, int out_size)
{
    const int*   input_seq = (const int*)d_in[0];
    const float* emb = (const float*)d_in[1];
    const float* W0  = (const float*)d_in[2];
    const float* b0  = (const float*)d_in[3];
    const float* W1  = (const float*)d_in[4];
    const float* b1  = (const float*)d_in[5];
    const float* Wd  = (const float*)d_in[6];
    const float* bd  = (const float*)d_in[7];
    float* out = (float*)d_out;
    (void)in_sizes; (void)n_in; (void)out_size;

    float *xemb, *gx, *hs0, *hs1, *h0, *h1, *cbuf;
    cudaGetSymbolAddress((void**)&xemb, g_xemb);
    cudaGetSymbolAddress((void**)&gx,   g_gx);
    cudaGetSymbolAddress((void**)&hs0,  g_hseq0);
    cudaGetSymbolAddress((void**)&hs1,  g_hseq1);
    cudaGetSymbolAddress((void**)&h0,   g_h0);
    cudaGetSymbolAddress((void**)&h1,   g_h1);
    cudaGetSymbolAddress((void**)&cbuf, g_c);

    size_t smem = (size_t)(32 * HP + 3 * 1024 + 32 * 33) * sizeof(float);
    cudaFuncSetAttribute(lstm_step, cudaFuncAttributeMaxDynamicSharedMemorySize, (int)smem);

    // 1) embedding
    embed_kernel<<<BT, 256>>>(input_seq, emb);

    // 2) layer-0 input-path gates: GX = Xemb @ W0[0:E] + b0
    dim3 gGX(G / 128, BT / 128);
    sgemm_bias<<<gGX, 256>>>(xemb, W0, b0, gx, BT, G, E);

    // 3) layer-0 recurrence
    zero_state_kernel<<<(B * H + 255) / 256, 256>>>();
    for (int t = 0; t < T; t++) {
        float* hin  = (t & 1) ? h1 : h0;
        float* hout = (t & 1) ? h0 : h1;
        lstm_step<<<128, 256, smem>>>(gx, W0 + (size_t)E * G, hin, hout, cbuf, hs0, t);
    }

    // 4) layer-1 input-path gates: GX = hseq0 @ W1[0:H] + b1
    sgemm_bias<<<gGX, 256>>>(hs0, W1, b1, gx, BT, G, H);

    // 5) layer-1 recurrence
    zero_state_kernel<<<(B * H + 255) / 256, 256>>>();
    for (int t = 0; t < T; t++) {
        float* hin  = (t & 1) ? h1 : h0;
        float* hout = (t & 1) ? h0 : h1;
        lstm_step<<<128, 256, smem>>>(gx, W1 + (size_t)H * G, hin, hout, cbuf, hs1, t);
    }

    // 6) dense projection: out = hseq1 @ Wd + bd
    dim3 gOUT(V / 128, BT / 128);
    sgemm_bias<<<gOUT, 256>>>(hs1, Wd, bd, out, BT, V, H);
}